// round 10
// baseline (speedup 1.0000x reference)
#include <cuda_runtime.h>
#include <cuda_bf16.h>
#include <mma.h>
#include <math.h>
#include <stdint.h>

using namespace nvcuda;

#define NB   4
#define SEQ  2048
#define DIM  1024
#define NH   16
#define DKH  64
#define MTOT (NB*SEQ)        // 8192

// Scratch (device globals: no allocations allowed)
__device__ float g_q[NB*NH*SEQ*DKH];
__device__ float g_k[NB*NH*SEQ*DKH];
__device__ float g_v[NB*NH*SEQ*DKH];
__device__ float g_att[NB*NH*SEQ*DKH];
__device__ float g_cos[SEQ*(DKH/2)];
__device__ float g_sin[SEQ*(DKH/2)];
// pre-split bf16 planes (hi/lo) for attention
__device__ __nv_bfloat16 g_qh[NB*NH*SEQ*DKH], g_ql[NB*NH*SEQ*DKH];
__device__ __nv_bfloat16 g_kh[NB*NH*SEQ*DKH], g_kl[NB*NH*SEQ*DKH];
__device__ __nv_bfloat16 g_vh[NB*NH*SEQ*DKH], g_vl[NB*NH*SEQ*DKH];

// ---------------------------------------------------------------------------
// Split helpers: fp32 -> bf16 hi + bf16 lo (residual)
// ---------------------------------------------------------------------------
__device__ __forceinline__ uint32_t bf2(float lo, float hi) {
    uint32_t r;
    asm("cvt.rn.bf16x2.f32 %0, %1, %2;" : "=r"(r) : "f"(hi), "f"(lo));
    return r;
}

__device__ __forceinline__ void split_store(uint32_t* ph, uint32_t* pl,
                                            int w, float4 v) {
    uint32_t hxy = bf2(v.x, v.y);
    uint32_t hzw = bf2(v.z, v.w);
    float fx = __uint_as_float(hxy << 16);
    float fy = __uint_as_float(hxy & 0xffff0000u);
    float fz = __uint_as_float(hzw << 16);
    float fw = __uint_as_float(hzw & 0xffff0000u);
    uint32_t lxy = bf2(v.x - fx, v.y - fy);
    uint32_t lzw = bf2(v.z - fz, v.w - fw);
    ph[w]     = hxy;
    ph[w + 1] = hzw;
    pl[w]     = lxy;
    pl[w + 1] = lzw;
}

// ---------------------------------------------------------------------------
// RoPE table
// ---------------------------------------------------------------------------
__global__ void rope_table_kernel(const int* __restrict__ pos) {
    int idx = blockIdx.x * blockDim.x + threadIdx.x;
    if (idx >= SEQ * (DKH/2)) return;
    int srow = idx >> 5;
    int i    = idx & 31;
    double freq = exp(-((double)(2*i) / (double)DKH) * log(10000.0));
    double ang  = (double)pos[srow] * freq;
    g_cos[idx] = (float)cos(ang);
    g_sin[idx] = (float)sin(ang);
}

// ---------------------------------------------------------------------------
// RoPE apply + split to bf16 planes. t=0: q(rope), t=1: k(rope), t=2: v(split).
// One thread per (even,odd) element pair.
// ---------------------------------------------------------------------------
__global__ void rope_split_kernel() {
    int idx = blockIdx.x * blockDim.x + threadIdx.x;   // < 3 * 2^22
    int t   = idx >> 22;
    int r   = idx & ((1 << 22) - 1);
    int i   = r & 31;
    int row = r >> 5;                                  // (b*NH+h)*SEQ + s
    int w   = (row << 5) + i;                          // u32 index in planes
    float oe, oo;
    uint32_t *ph, *pl;
    if (t == 2) {
        float2 v = *(const float2*)(g_v + (row << 6) + (i << 1));
        oe = v.x; oo = v.y;
        ph = (uint32_t*)g_vh; pl = (uint32_t*)g_vl;
    } else {
        int srow = row & (SEQ - 1);
        float c = g_cos[(srow << 5) + i];
        float s = g_sin[(srow << 5) + i];
        const float* p = (t ? g_k : g_q) + (row << 6) + (i << 1);
        float2 v = *(const float2*)p;
        oe = c * v.x - s * v.y;
        oo = s * v.x + c * v.y;
        ph = (uint32_t*)(t ? g_kh : g_qh);
        pl = (uint32_t*)(t ? g_kl : g_ql);
    }
    uint32_t h = bf2(oe, oo);
    float fe = __uint_as_float(h << 16);
    float fo = __uint_as_float(h & 0xffff0000u);
    ph[w] = h;
    pl[w] = bf2(oe - fe, oo - fo);
}

// ---------------------------------------------------------------------------
// WMMA NT GEMM, split-bf16 x3, BK=16, 2-stage smem double buffer.
// Block 128x128, 8 warps, warp tile 32x64. smem exactly 48KB static.
// AMODE 0: A row-major. AMODE 1: gather from g_att. CDST 0: Cout; 1/2/3: bhsd.
// ---------------------------------------------------------------------------
#define GK   16
#define GLD  24    // bf16 per smem row (16 data + 8 pad); 48B, conflict-free

template<int AMODE>
__device__ __forceinline__ float4 ld_a4(const float* __restrict__ A, int aRow, int k) {
    if (AMODE == 0) {
        return *(const float4*)(A + aRow * DIM + k);
    } else {
        int head = k >> 6, koff = k & 63;
        int bq = aRow >> 11, srow = aRow & (SEQ - 1);
        return *(const float4*)(g_att + (((bq << 4) + head) * SEQ + srow) * DKH + koff);
    }
}

template<int AMODE, int CDST>
__global__ __launch_bounds__(256, 2)
void gemm_wmma_kernel(const float* __restrict__ A,
                      const float* __restrict__ W,
                      float* __restrict__ Cout) {
    __shared__ __align__(16) uint32_t sAh[2][128 * GLD / 2];
    __shared__ __align__(16) uint32_t sAl[2][128 * GLD / 2];
    __shared__ __align__(16) uint32_t sBh[2][128 * GLD / 2];
    __shared__ __align__(16) uint32_t sBl[2][128 * GLD / 2];

    const int bn  = blockIdx.x;
    const int bm  = blockIdx.y;
    const int tid = threadIdx.x;
    const int wid = tid >> 5;
    const int wm  = wid & 3;
    const int wn  = wid >> 2;
    const int lrow = tid >> 2;          // 0..63? no: c>>2 below
    (void)lrow;

    typedef wmma::fragment<wmma::matrix_a, 16, 16, 16, __nv_bfloat16, wmma::row_major> FragA;
    typedef wmma::fragment<wmma::matrix_b, 16, 16, 16, __nv_bfloat16, wmma::col_major> FragB;
    typedef wmma::fragment<wmma::accumulator, 16, 16, 16, float> FragC;

    FragC acc[2][4];
    #pragma unroll
    for (int i = 0; i < 2; i++)
        #pragma unroll
        for (int j = 0; j < 4; j++) wmma::fill_fragment(acc[i][j], 0.0f);

    float4 av[2], wv[2];
    #pragma unroll
    for (int j = 0; j < 2; ++j) {
        int c = tid + j * 256, row = c >> 2, k4 = c & 3;
        av[j] = ld_a4<AMODE>(A, bm * 128 + row, k4 * 4);
        wv[j] = *(const float4*)(W + (bn * 128 + row) * DIM + k4 * 4);
    }
    #pragma unroll
    for (int j = 0; j < 2; ++j) {
        int c = tid + j * 256, row = c >> 2, k4 = c & 3;
        split_store(sAh[0], sAl[0], row * (GLD/2) + k4 * 2, av[j]);
        split_store(sBh[0], sBl[0], row * (GLD/2) + k4 * 2, wv[j]);
    }
    __syncthreads();

    for (int kt = 0; kt < DIM / GK; ++kt) {
        const int buf = kt & 1;
        if (kt + 1 < DIM / GK) {
            #pragma unroll
            for (int j = 0; j < 2; ++j) {
                int c = tid + j * 256, row = c >> 2, k4 = c & 3;
                av[j] = ld_a4<AMODE>(A, bm * 128 + row, (kt + 1) * GK + k4 * 4);
                wv[j] = *(const float4*)(W + (bn * 128 + row) * DIM + (kt + 1) * GK + k4 * 4);
            }
        }

        const __nv_bfloat16* pAh = (const __nv_bfloat16*)sAh[buf];
        const __nv_bfloat16* pAl = (const __nv_bfloat16*)sAl[buf];
        const __nv_bfloat16* pBh = (const __nv_bfloat16*)sBh[buf];
        const __nv_bfloat16* pBl = (const __nv_bfloat16*)sBl[buf];
        FragA ah[2], al[2];
        #pragma unroll
        for (int i = 0; i < 2; i++) {
            wmma::load_matrix_sync(ah[i], pAh + (wm * 32 + i * 16) * GLD, GLD);
            wmma::load_matrix_sync(al[i], pAl + (wm * 32 + i * 16) * GLD, GLD);
        }
        #pragma unroll
        for (int j = 0; j < 4; j++) {
            FragB bh, bl;
            wmma::load_matrix_sync(bh, pBh + (wn * 64 + j * 16) * GLD, GLD);
            wmma::load_matrix_sync(bl, pBl + (wn * 64 + j * 16) * GLD, GLD);
            #pragma unroll
            for (int i = 0; i < 2; i++) {
                wmma::mma_sync(acc[i][j], ah[i], bh, acc[i][j]);
                wmma::mma_sync(acc[i][j], ah[i], bl, acc[i][j]);
                wmma::mma_sync(acc[i][j], al[i], bh, acc[i][j]);
            }
        }

        if (kt + 1 < DIM / GK) {
            const int nb = buf ^ 1;
            #pragma unroll
            for (int j = 0; j < 2; ++j) {
                int c = tid + j * 256, row = c >> 2, k4 = c & 3;
                split_store(sAh[nb], sAl[nb], row * (GLD/2) + k4 * 2, av[j]);
                split_store(sBh[nb], sBl[nb], row * (GLD/2) + k4 * 2, wv[j]);
            }
        }
        __syncthreads();
    }

    #pragma unroll
    for (int i = 0; i < 2; i++) {
        int r0 = bm * 128 + wm * 32 + i * 16;
        #pragma unroll
        for (int j = 0; j < 4; j++) {
            int c0 = bn * 128 + wn * 64 + j * 16;
            if (CDST == 0) {
                wmma::store_matrix_sync(Cout + r0 * DIM + c0, acc[i][j], DIM,
                                        wmma::mem_row_major);
            } else {
                float* base = (CDST == 1) ? g_q : (CDST == 2) ? g_k : g_v;
                int head = c0 >> 6, koff = c0 & 63;
                int bq = r0 >> 11, srow = r0 & (SEQ - 1);
                wmma::store_matrix_sync(
                    base + (((bq << 4) + head) * SEQ + srow) * DKH + koff,
                    acc[i][j], DKH, wmma::mem_row_major);
            }
        }
    }
}

// ---------------------------------------------------------------------------
// WMMA flash attention, pre-split bf16 planes (no convert in inner loop).
// Block 128 threads (4 warps); tile 32 q-rows x 32 keys; dk=64.
// smem: Q/K/V hi+lo planes (stride 72 bf16 = 9 uint4 rows), S f32(36), O f32(68).
// ---------------------------------------------------------------------------
#define PSTR 72
#define SSTR 36
#define OSTR 68

__global__ __launch_bounds__(128)
void attn_wmma_kernel() {
    __shared__ __align__(16) __nv_bfloat16 sQh[32*PSTR], sQl[32*PSTR];
    __shared__ __align__(16) __nv_bfloat16 sKh[32*PSTR], sKl[32*PSTR];
    __shared__ __align__(16) __nv_bfloat16 sVh[32*PSTR], sVl[32*PSTR];
    __shared__ __align__(16) float sS[32*SSTR];
    __shared__ __align__(16) float sO[32*OSTR];

    const int qt  = 63 - (int)blockIdx.x;   // heavy q-tiles first
    const int bh  = blockIdx.y;
    const int tid = threadIdx.x;
    const int wid = tid >> 5;
    const int wm  = wid & 1;
    const int wn  = wid >> 1;

    typedef wmma::fragment<wmma::matrix_a, 16, 16, 16, __nv_bfloat16, wmma::row_major> FragA;
    typedef wmma::fragment<wmma::matrix_b, 16, 16, 16, __nv_bfloat16, wmma::col_major> FragBT;
    typedef wmma::fragment<wmma::matrix_b, 16, 16, 16, __nv_bfloat16, wmma::row_major> FragBN;
    typedef wmma::fragment<wmma::accumulator, 16, 16, 16, float> FragC;

    // copy Q tile planes: 32 rows x 64 bf16 = 8 uint4/row, dest stride 9 uint4
    {
        const uint4* qh = (const uint4*)(g_qh + (bh * SEQ + qt * 32) * DKH);
        const uint4* ql = (const uint4*)(g_ql + (bh * SEQ + qt * 32) * DKH);
        #pragma unroll
        for (int j = 0; j < 2; ++j) {
            int c = tid + j * 128;          // 0..255
            int row = c >> 3, s = c & 7;
            ((uint4*)sQh)[row * 9 + s] = qh[row * 8 + s];
            ((uint4*)sQl)[row * 9 + s] = ql[row * 8 + s];
        }
    }
    #pragma unroll
    for (int j = 0; j < 17; ++j) sO[tid + j * 128] = 0.f;

    const int r  = tid >> 2;
    const int tc = tid & 3;
    float M = -INFINITY, L = 0.f;
    __syncthreads();

    for (int kt = 0; kt <= qt; ++kt) {
        {
            const uint4* kh = (const uint4*)(g_kh + (bh * SEQ + kt * 32) * DKH);
            const uint4* kl = (const uint4*)(g_kl + (bh * SEQ + kt * 32) * DKH);
            const uint4* vh = (const uint4*)(g_vh + (bh * SEQ + kt * 32) * DKH);
            const uint4* vl = (const uint4*)(g_vl + (bh * SEQ + kt * 32) * DKH);
            #pragma unroll
            for (int j = 0; j < 2; ++j) {
                int c = tid + j * 128;
                int row = c >> 3, s = c & 7;
                ((uint4*)sKh)[row * 9 + s] = kh[row * 8 + s];
                ((uint4*)sKl)[row * 9 + s] = kl[row * 8 + s];
                ((uint4*)sVh)[row * 9 + s] = vh[row * 8 + s];
                ((uint4*)sVl)[row * 9 + s] = vl[row * 8 + s];
            }
        }
        __syncthreads();

        // S = Q K^T
        {
            FragC sf;
            wmma::fill_fragment(sf, 0.f);
            #pragma unroll
            for (int ks = 0; ks < 4; ++ks) {
                FragA qh, ql;
                FragBT kh, kl;
                wmma::load_matrix_sync(qh, sQh + wm * 16 * PSTR + ks * 16, PSTR);
                wmma::load_matrix_sync(ql, sQl + wm * 16 * PSTR + ks * 16, PSTR);
                wmma::load_matrix_sync(kh, sKh + wn * 16 * PSTR + ks * 16, PSTR);
                wmma::load_matrix_sync(kl, sKl + wn * 16 * PSTR + ks * 16, PSTR);
                wmma::mma_sync(sf, qh, kh, sf);
                wmma::mma_sync(sf, qh, kl, sf);
                wmma::mma_sync(sf, ql, kh, sf);
            }
            wmma::store_matrix_sync(sS + wm * 16 * SSTR + wn * 16, sf, SSTR,
                                    wmma::mem_row_major);
        }
        __syncthreads();

        // online softmax: 4 threads per row, 8 cols each
        float p[8];
        const int qglob = qt * 32 + r;
        const int c0 = tc * 8;
        float mloc = -INFINITY;
        #pragma unroll
        for (int i = 0; i < 8; ++i) {
            float s = sS[r * SSTR + c0 + i] * 0.125f;
            if (kt * 32 + c0 + i > qglob) s = -INFINITY;
            p[i] = s;
            mloc = fmaxf(mloc, s);
        }
        mloc = fmaxf(mloc, __shfl_xor_sync(0xffffffffu, mloc, 1));
        mloc = fmaxf(mloc, __shfl_xor_sync(0xffffffffu, mloc, 2));
        float Mn = fmaxf(M, mloc);
        float al = __expf(M - Mn);
        M = Mn;
        float rs = 0.f;
        #pragma unroll
        for (int i = 0; i < 8; ++i) { p[i] = __expf(p[i] - Mn); rs += p[i]; }
        rs += __shfl_xor_sync(0xffffffffu, rs, 1);
        rs += __shfl_xor_sync(0xffffffffu, rs, 2);
        L = L * al + rs;

        // write P split into the (now free) K planes
        #pragma unroll
        for (int i = 0; i < 4; ++i) {
            uint32_t h = bf2(p[2*i], p[2*i+1]);
            float fx = __uint_as_float(h << 16);
            float fy = __uint_as_float(h & 0xffff0000u);
            uint32_t lo = bf2(p[2*i] - fx, p[2*i+1] - fy);
            ((uint32_t*)sKh)[r * (PSTR/2) + tc * 4 + i] = h;
            ((uint32_t*)sKl)[r * (PSTR/2) + tc * 4 + i] = lo;
        }
        // rescale O row by al
        #pragma unroll
        for (int i = 0; i < 4; ++i) {
            float4* po = (float4*)&sO[r * OSTR + tc * 16 + i * 4];
            float4 v = *po;
            v.x *= al; v.y *= al; v.z *= al; v.w *= al;
            *po = v;
        }
        __syncthreads();

        // O += P V
        {
            FragC of[2];
            #pragma unroll
            for (int j = 0; j < 2; ++j)
                wmma::load_matrix_sync(of[j], sO + wm * 16 * OSTR + wn * 32 + j * 16,
                                       OSTR, wmma::mem_row_major);
            #pragma unroll
            for (int ks = 0; ks < 2; ++ks) {
                FragA ph, pl;
                wmma::load_matrix_sync(ph, sKh + wm * 16 * PSTR + ks * 16, PSTR);
                wmma::load_matrix_sync(pl, sKl + wm * 16 * PSTR + ks * 16, PSTR);
                #pragma unroll
                for (int j = 0; j < 2; ++j) {
                    FragBN vh, vl;
                    wmma::load_matrix_sync(vh, sVh + ks * 16 * PSTR + wn * 32 + j * 16, PSTR);
                    wmma::load_matrix_sync(vl, sVl + ks * 16 * PSTR + wn * 32 + j * 16, PSTR);
                    wmma::mma_sync(of[j], ph, vh, of[j]);
                    wmma::mma_sync(of[j], ph, vl, of[j]);
                    wmma::mma_sync(of[j], pl, vh, of[j]);
                }
            }
            #pragma unroll
            for (int j = 0; j < 2; ++j)
                wmma::store_matrix_sync(sO + wm * 16 * OSTR + wn * 32 + j * 16, of[j],
                                        OSTR, wmma::mem_row_major);
        }
        __syncthreads();
    }

    float inv = 1.f / L;
    float* ob = g_att + (bh * SEQ + qt * 32) * DKH;
    #pragma unroll
    for (int i = 0; i < 4; ++i) {
        float4 v = *(float4*)&sO[r * OSTR + tc * 16 + i * 4];
        v.x *= inv; v.y *= inv; v.z *= inv; v.w *= inv;
        *(float4*)(ob + r * DKH + tc * 16 + i * 4) = v;
    }
}

// ---------------------------------------------------------------------------
extern "C" void kernel_launch(void* const* d_in, const int* in_sizes, int n_in,
                              void* d_out, int out_size) {
    (void)in_sizes; (void)n_in; (void)out_size;
    const float* x   = (const float*)d_in[0];
    const float* Wq  = (const float*)d_in[1];
    const float* Wk  = (const float*)d_in[2];
    const float* Wv  = (const float*)d_in[3];
    const float* Wo  = (const float*)d_in[4];
    const int*   pos = (const int*)d_in[5];
    float* out = (float*)d_out;

    rope_table_kernel<<<(SEQ * 32 + 255) / 256, 256>>>(pos);

    dim3 ggrid(DIM / 128, MTOT / 128);   // (8, 64)
    gemm_wmma_kernel<0, 1><<<ggrid, 256>>>(x, Wq, nullptr);
    gemm_wmma_kernel<0, 2><<<ggrid, 256>>>(x, Wk, nullptr);
    gemm_wmma_kernel<0, 3><<<ggrid, 256>>>(x, Wv, nullptr);

    rope_split_kernel<<<(3 * NB * NH * SEQ * 32) / 256, 256>>>();

    attn_wmma_kernel<<<dim3(SEQ / 32, NB * NH), 128>>>();

    gemm_wmma_kernel<1, 0><<<ggrid, 256>>>(nullptr, Wo, out);
}

// round 11
// speedup vs baseline: 1.5127x; 1.5127x over previous
#include <cuda_runtime.h>
#include <cuda_bf16.h>
#include <mma.h>
#include <math.h>
#include <stdint.h>

using namespace nvcuda;

#define NB   4
#define SEQ  2048
#define DIM  1024
#define NH   16
#define DKH  64
#define MTOT (NB*SEQ)        // 8192

// Scratch (device globals: no allocations allowed)
__device__ float g_q[NB*NH*SEQ*DKH];
__device__ float g_k[NB*NH*SEQ*DKH];
__device__ float g_v[NB*NH*SEQ*DKH];
__device__ float g_att[NB*NH*SEQ*DKH];
__device__ float g_cos[SEQ*(DKH/2)];
__device__ float g_sin[SEQ*(DKH/2)];
// pre-split bf16 planes (hi/lo) for attention
__device__ __nv_bfloat16 g_qh[NB*NH*SEQ*DKH], g_ql[NB*NH*SEQ*DKH];
__device__ __nv_bfloat16 g_kh[NB*NH*SEQ*DKH], g_kl[NB*NH*SEQ*DKH];
__device__ __nv_bfloat16 g_vh[NB*NH*SEQ*DKH], g_vl[NB*NH*SEQ*DKH];

// ---------------------------------------------------------------------------
// Helpers
// ---------------------------------------------------------------------------
__device__ __forceinline__ uint32_t bf2(float lo, float hi) {
    uint32_t r;
    asm("cvt.rn.bf16x2.f32 %0, %1, %2;" : "=r"(r) : "f"(hi), "f"(lo));
    return r;
}

__device__ __forceinline__ void split_store(uint32_t* ph, uint32_t* pl,
                                            int w, float4 v) {
    uint32_t hxy = bf2(v.x, v.y);
    uint32_t hzw = bf2(v.z, v.w);
    float fx = __uint_as_float(hxy << 16);
    float fy = __uint_as_float(hxy & 0xffff0000u);
    float fz = __uint_as_float(hzw << 16);
    float fw = __uint_as_float(hzw & 0xffff0000u);
    uint32_t lxy = bf2(v.x - fx, v.y - fy);
    uint32_t lzw = bf2(v.z - fz, v.w - fw);
    ph[w]     = hxy;
    ph[w + 1] = hzw;
    pl[w]     = lxy;
    pl[w + 1] = lzw;
}

__device__ __forceinline__ uint32_t smem_u32(const void* p) {
    uint32_t a;
    asm("{ .reg .u64 t; cvta.to.shared.u64 t, %1; cvt.u32.u64 %0, t; }"
        : "=r"(a) : "l"(p));
    return a;
}

__device__ __forceinline__ void ldsm4(uint32_t& r0, uint32_t& r1,
                                      uint32_t& r2, uint32_t& r3, uint32_t a) {
    asm volatile("ldmatrix.sync.aligned.m8n8.x4.shared.b16 {%0,%1,%2,%3}, [%4];"
                 : "=r"(r0), "=r"(r1), "=r"(r2), "=r"(r3) : "r"(a));
}
__device__ __forceinline__ void ldsm4t(uint32_t& r0, uint32_t& r1,
                                       uint32_t& r2, uint32_t& r3, uint32_t a) {
    asm volatile("ldmatrix.sync.aligned.m8n8.x4.trans.shared.b16 {%0,%1,%2,%3}, [%4];"
                 : "=r"(r0), "=r"(r1), "=r"(r2), "=r"(r3) : "r"(a));
}

__device__ __forceinline__ void mma16816(float d[4],
                                         uint32_t a0, uint32_t a1, uint32_t a2, uint32_t a3,
                                         uint32_t b0, uint32_t b1) {
    asm volatile(
        "mma.sync.aligned.m16n8k16.row.col.f32.bf16.bf16.f32 "
        "{%0,%1,%2,%3}, {%4,%5,%6,%7}, {%8,%9}, {%0,%1,%2,%3};"
        : "+f"(d[0]), "+f"(d[1]), "+f"(d[2]), "+f"(d[3])
        : "r"(a0), "r"(a1), "r"(a2), "r"(a3), "r"(b0), "r"(b1));
}

// swizzled smem address for one 16B unit of a [64 rows][8 units] plane
// ldmatrix x4 lane address: g = lane>>3 selects matrix, r = lane&7 its row.
__device__ __forceinline__ uint32_t lda(uint32_t base, int row0, int cbase, int lane) {
    int g = lane >> 3, r = lane & 7;
    int row = row0 + ((g & 1) << 3) + r;
    int c = cbase + (g >> 1);
    return base + (((row << 3) + (c ^ (row & 7))) << 4);
}

// ---------------------------------------------------------------------------
// RoPE table
// ---------------------------------------------------------------------------
__global__ void rope_table_kernel(const int* __restrict__ pos) {
    int idx = blockIdx.x * blockDim.x + threadIdx.x;
    if (idx >= SEQ * (DKH/2)) return;
    int srow = idx >> 5;
    int i    = idx & 31;
    double freq = exp(-((double)(2*i) / (double)DKH) * log(10000.0));
    double ang  = (double)pos[srow] * freq;
    g_cos[idx] = (float)cos(ang);
    g_sin[idx] = (float)sin(ang);
}

// ---------------------------------------------------------------------------
// RoPE apply + split to bf16 planes. t=0: q(rope), t=1: k(rope), t=2: v(split).
// ---------------------------------------------------------------------------
__global__ void rope_split_kernel() {
    int idx = blockIdx.x * blockDim.x + threadIdx.x;   // < 3 * 2^22
    int t   = idx >> 22;
    int r   = idx & ((1 << 22) - 1);
    int i   = r & 31;
    int row = r >> 5;                                  // (b*NH+h)*SEQ + s
    int w   = (row << 5) + i;                          // u32 index in planes
    float oe, oo;
    uint32_t *ph, *pl;
    if (t == 2) {
        float2 v = *(const float2*)(g_v + (row << 6) + (i << 1));
        oe = v.x; oo = v.y;
        ph = (uint32_t*)g_vh; pl = (uint32_t*)g_vl;
    } else {
        int srow = row & (SEQ - 1);
        float c = g_cos[(srow << 5) + i];
        float s = g_sin[(srow << 5) + i];
        const float* p = (t ? g_k : g_q) + (row << 6) + (i << 1);
        float2 v = *(const float2*)p;
        oe = c * v.x - s * v.y;
        oo = s * v.x + c * v.y;
        ph = (uint32_t*)(t ? g_kh : g_qh);
        pl = (uint32_t*)(t ? g_kl : g_ql);
    }
    uint32_t h = bf2(oe, oo);
    float fe = __uint_as_float(h << 16);
    float fo = __uint_as_float(h & 0xffff0000u);
    ph[w] = h;
    pl[w] = bf2(oe - fe, oo - fo);
}

// ---------------------------------------------------------------------------
// WMMA NT GEMM, split-bf16 x3 passes (R9 version, 194.8us, known good).
// ---------------------------------------------------------------------------
#define LDAB 40

template<int AMODE>
__device__ __forceinline__ float4 ld_a4(const float* __restrict__ A, int aRow, int k) {
    if (AMODE == 0) {
        return *(const float4*)(A + aRow * DIM + k);
    } else {
        int head = k >> 6, koff = k & 63;
        int bq = aRow >> 11, srow = aRow & (SEQ - 1);
        return *(const float4*)(g_att + (((bq << 4) + head) * SEQ + srow) * DKH + koff);
    }
}

template<int AMODE, int CDST>
__global__ __launch_bounds__(256, 2)
void gemm_wmma_kernel(const float* __restrict__ A,
                      const float* __restrict__ W,
                      float* __restrict__ Cout) {
    __shared__ __align__(16) uint32_t sAh[128 * LDAB / 2];
    __shared__ __align__(16) uint32_t sAl[128 * LDAB / 2];
    __shared__ __align__(16) uint32_t sBh[128 * LDAB / 2];
    __shared__ __align__(16) uint32_t sBl[128 * LDAB / 2];

    const int bn  = blockIdx.x;
    const int bm  = blockIdx.y;
    const int tid = threadIdx.x;
    const int wid = tid >> 5;
    const int wm  = wid & 3;
    const int wn  = wid >> 2;

    typedef wmma::fragment<wmma::matrix_a, 16, 16, 16, __nv_bfloat16, wmma::row_major> FragA;
    typedef wmma::fragment<wmma::matrix_b, 16, 16, 16, __nv_bfloat16, wmma::col_major> FragB;
    typedef wmma::fragment<wmma::accumulator, 16, 16, 16, float> FragC;

    FragC acc[2][4];
    #pragma unroll
    for (int i = 0; i < 2; i++)
        #pragma unroll
        for (int j = 0; j < 4; j++) wmma::fill_fragment(acc[i][j], 0.0f);

    const __nv_bfloat16* pAh = (const __nv_bfloat16*)sAh;
    const __nv_bfloat16* pAl = (const __nv_bfloat16*)sAl;
    const __nv_bfloat16* pBh = (const __nv_bfloat16*)sBh;
    const __nv_bfloat16* pBl = (const __nv_bfloat16*)sBl;

    for (int kt = 0; kt < DIM / 32; ++kt) {
        #pragma unroll
        for (int j = 0; j < 4; ++j) {
            int c   = tid + j * 256;
            int row = c >> 3;
            int k4  = c & 7;
            float4 v = ld_a4<AMODE>(A, bm * 128 + row, kt * 32 + k4 * 4);
            split_store(sAh, sAl, row * (LDAB / 2) + k4 * 2, v);
        }
        #pragma unroll
        for (int j = 0; j < 4; ++j) {
            int c   = tid + j * 256;
            int row = c >> 3;
            int k4  = c & 7;
            float4 v = *(const float4*)(W + (bn * 128 + row) * DIM + kt * 32 + k4 * 4);
            split_store(sBh, sBl, row * (LDAB / 2) + k4 * 2, v);
        }
        __syncthreads();

        #pragma unroll
        for (int ks = 0; ks < 2; ++ks) {
            FragA ah[2], al[2];
            #pragma unroll
            for (int i = 0; i < 2; i++) {
                wmma::load_matrix_sync(ah[i], pAh + (wm * 32 + i * 16) * LDAB + ks * 16, LDAB);
                wmma::load_matrix_sync(al[i], pAl + (wm * 32 + i * 16) * LDAB + ks * 16, LDAB);
            }
            #pragma unroll
            for (int j = 0; j < 4; j++) {
                FragB bh, bl;
                wmma::load_matrix_sync(bh, pBh + (wn * 64 + j * 16) * LDAB + ks * 16, LDAB);
                wmma::load_matrix_sync(bl, pBl + (wn * 64 + j * 16) * LDAB + ks * 16, LDAB);
                #pragma unroll
                for (int i = 0; i < 2; i++) {
                    wmma::mma_sync(acc[i][j], ah[i], bh, acc[i][j]);
                    wmma::mma_sync(acc[i][j], ah[i], bl, acc[i][j]);
                    wmma::mma_sync(acc[i][j], al[i], bh, acc[i][j]);
                }
            }
        }
        __syncthreads();
    }

    #pragma unroll
    for (int i = 0; i < 2; i++) {
        int r0 = bm * 128 + wm * 32 + i * 16;
        #pragma unroll
        for (int j = 0; j < 4; j++) {
            int c0 = bn * 128 + wn * 64 + j * 16;
            if (CDST == 0) {
                wmma::store_matrix_sync(Cout + r0 * DIM + c0, acc[i][j], DIM,
                                        wmma::mem_row_major);
            } else {
                float* base = (CDST == 1) ? g_q : (CDST == 2) ? g_k : g_v;
                int head = c0 >> 6, koff = c0 & 63;
                int bq = r0 >> 11, srow = r0 & (SEQ - 1);
                wmma::store_matrix_sync(
                    base + (((bq << 4) + head) * SEQ + srow) * DKH + koff,
                    acc[i][j], DKH, wmma::mem_row_major);
            }
        }
    }
}

// ---------------------------------------------------------------------------
// FA2 attention with raw mma.sync.m16n8k16, register-resident S/P/O.
// 128 threads / 4 warps; q-tile 64 (16 rows per warp), key-tile 64, dk=64.
// smem 32KB: Kh/Kl/Vh/Vl planes [64][64] bf16, XOR-swizzled 16B units.
// Q planes alias the K region before the loop (consumed into registers).
// Split-bf16 x3 passes for both QK^T and PV.
// ---------------------------------------------------------------------------
__global__ __launch_bounds__(128)
void attn_mma_kernel() {
    __shared__ __align__(16) uint4 sbuf4[2048];     // 32 KB
    char* sb = (char*)sbuf4;
    const uint32_t sbase = smem_u32(sb);
    const uint32_t bKh = 0, bKl = 8192, bVh = 16384, bVl = 24576;

    const int qt  = (int)(gridDim.x - 1 - blockIdx.x);   // heavy q-tiles first
    const int bh  = blockIdx.y;
    const int tid = threadIdx.x;
    const int w   = tid >> 5;
    const int l   = tid & 31;

    const int qoff = (bh * SEQ + qt * 64) * DKH;

    // ---- stage Q planes into smem (aliasing K region), then to registers
    {
        const uint4* qh = (const uint4*)(g_qh + qoff);
        const uint4* ql = (const uint4*)(g_ql + qoff);
        #pragma unroll
        for (int j = 0; j < 4; ++j) {
            int u = tid + j * 128;                  // 0..511
            int row = u >> 3, c = u & 7;
            uint32_t so = ((row << 3) + (c ^ (row & 7))) << 4;
            *(uint4*)(sb + bKh + so) = qh[u];
            *(uint4*)(sb + bKl + so) = ql[u];
        }
    }
    __syncthreads();

    uint32_t Qh[4][4], Ql[4][4];
    #pragma unroll
    for (int kc = 0; kc < 4; ++kc) {
        ldsm4(Qh[kc][0], Qh[kc][1], Qh[kc][2], Qh[kc][3],
              lda(sbase + bKh, w * 16, kc * 2, l));
        ldsm4(Ql[kc][0], Ql[kc][1], Ql[kc][2], Ql[kc][3],
              lda(sbase + bKl, w * 16, kc * 2, l));
    }
    __syncthreads();

    float O[8][4];
    #pragma unroll
    for (int j = 0; j < 8; ++j)
        #pragma unroll
        for (int c = 0; c < 4; ++c) O[j][c] = 0.f;
    float M0 = -INFINITY, M1 = -INFINITY, L0 = 0.f, L1 = 0.f;

    const int rr0 = w * 16 + (l >> 2);      // q row (c0,c1), tile-local
    const int rr1 = rr0 + 8;                // q row (c2,c3)
    const int kb  = (l & 3) * 2;            // key col base within n8 tile

    for (int kt = 0; kt <= qt; ++kt) {
        // ---- stage K/V hi/lo planes
        {
            const int koff = (bh * SEQ + kt * 64) * DKH;
            const uint4* s0 = (const uint4*)(g_kh + koff);
            const uint4* s1 = (const uint4*)(g_kl + koff);
            const uint4* s2 = (const uint4*)(g_vh + koff);
            const uint4* s3 = (const uint4*)(g_vl + koff);
            #pragma unroll
            for (int j = 0; j < 4; ++j) {
                int u = tid + j * 128;
                int row = u >> 3, c = u & 7;
                uint32_t so = ((row << 3) + (c ^ (row & 7))) << 4;
                *(uint4*)(sb + bKh + so) = s0[u];
                *(uint4*)(sb + bKl + so) = s1[u];
                *(uint4*)(sb + bVh + so) = s2[u];
                *(uint4*)(sb + bVl + so) = s3[u];
            }
        }
        __syncthreads();

        // ---- S = Q K^T (16 q-rows x 64 keys per warp), 3 passes
        float S[8][4];
        #pragma unroll
        for (int t = 0; t < 8; ++t)
            #pragma unroll
            for (int c = 0; c < 4; ++c) S[t][c] = 0.f;

        #pragma unroll
        for (int kc = 0; kc < 4; ++kc) {
            #pragma unroll
            for (int kg = 0; kg < 4; ++kg) {
                uint32_t kh[4], klr[4];
                ldsm4(kh[0], kh[1], kh[2], kh[3],
                      lda(sbase + bKh, kg * 16, kc * 2, l));
                ldsm4(klr[0], klr[1], klr[2], klr[3],
                      lda(sbase + bKl, kg * 16, kc * 2, l));
                // B frag (keys kg*16+0..7):   {r0, r2}; (+8..15): {r1, r3}
                mma16816(S[2*kg],   Qh[kc][0], Qh[kc][1], Qh[kc][2], Qh[kc][3], kh[0],  kh[2]);
                mma16816(S[2*kg],   Qh[kc][0], Qh[kc][1], Qh[kc][2], Qh[kc][3], klr[0], klr[2]);
                mma16816(S[2*kg],   Ql[kc][0], Ql[kc][1], Ql[kc][2], Ql[kc][3], kh[0],  kh[2]);
                mma16816(S[2*kg+1], Qh[kc][0], Qh[kc][1], Qh[kc][2], Qh[kc][3], kh[1],  kh[3]);
                mma16816(S[2*kg+1], Qh[kc][0], Qh[kc][1], Qh[kc][2], Qh[kc][3], klr[1], klr[3]);
                mma16816(S[2*kg+1], Ql[kc][0], Ql[kc][1], Ql[kc][2], Ql[kc][3], kh[1],  kh[3]);
            }
        }

        // ---- scale + causal mask (diagonal tile only)
        const bool diag = (kt == qt);
        #pragma unroll
        for (int t = 0; t < 8; ++t) {
            #pragma unroll
            for (int c = 0; c < 4; ++c) {
                float s = S[t][c] * 0.125f;
                if (diag) {
                    int key = t * 8 + kb + (c & 1);
                    int row = (c < 2) ? rr0 : rr1;
                    if (key > row) s = -INFINITY;
                }
                S[t][c] = s;
            }
        }

        // ---- online softmax (warp-local; rows live in 4-lane groups)
        float m0 = -INFINITY, m1 = -INFINITY;
        #pragma unroll
        for (int t = 0; t < 8; ++t) {
            m0 = fmaxf(m0, fmaxf(S[t][0], S[t][1]));
            m1 = fmaxf(m1, fmaxf(S[t][2], S[t][3]));
        }
        m0 = fmaxf(m0, __shfl_xor_sync(0xffffffffu, m0, 1));
        m0 = fmaxf(m0, __shfl_xor_sync(0xffffffffu, m0, 2));
        m1 = fmaxf(m1, __shfl_xor_sync(0xffffffffu, m1, 1));
        m1 = fmaxf(m1, __shfl_xor_sync(0xffffffffu, m1, 2));
        float Mn0 = fmaxf(M0, m0), Mn1 = fmaxf(M1, m1);
        float al0 = __expf(M0 - Mn0), al1 = __expf(M1 - Mn1);
        M0 = Mn0; M1 = Mn1;
        float rs0 = 0.f, rs1 = 0.f;
        #pragma unroll
        for (int t = 0; t < 8; ++t) {
            S[t][0] = __expf(S[t][0] - Mn0);
            S[t][1] = __expf(S[t][1] - Mn0);
            S[t][2] = __expf(S[t][2] - Mn1);
            S[t][3] = __expf(S[t][3] - Mn1);
            rs0 += S[t][0] + S[t][1];
            rs1 += S[t][2] + S[t][3];
        }
        rs0 += __shfl_xor_sync(0xffffffffu, rs0, 1);
        rs0 += __shfl_xor_sync(0xffffffffu, rs0, 2);
        rs1 += __shfl_xor_sync(0xffffffffu, rs1, 1);
        rs1 += __shfl_xor_sync(0xffffffffu, rs1, 2);
        L0 = L0 * al0 + rs0;
        L1 = L1 * al1 + rs1;
        #pragma unroll
        for (int j = 0; j < 8; ++j) {
            O[j][0] *= al0; O[j][1] *= al0;
            O[j][2] *= al1; O[j][3] *= al1;
        }

        // ---- O += P V (3 passes), P packed from S registers
        #pragma unroll
        for (int kc = 0; kc < 4; ++kc) {
            // A frags for keys kc*16..+15 from S tiles 2kc, 2kc+1
            uint32_t pa0 = bf2(S[2*kc][0],   S[2*kc][1]);
            uint32_t pa1 = bf2(S[2*kc][2],   S[2*kc][3]);
            uint32_t pa2 = bf2(S[2*kc+1][0], S[2*kc+1][1]);
            uint32_t pa3 = bf2(S[2*kc+1][2], S[2*kc+1][3]);
            // residual (lo) frags
            float f;
            uint32_t pl0, pl1, pl2, pl3;
            f = __uint_as_float(pa0 << 16);
            float fg = __uint_as_float(pa0 & 0xffff0000u);
            pl0 = bf2(S[2*kc][0] - f, S[2*kc][1] - fg);
            f = __uint_as_float(pa1 << 16);
            fg = __uint_as_float(pa1 & 0xffff0000u);
            pl1 = bf2(S[2*kc][2] - f, S[2*kc][3] - fg);
            f = __uint_as_float(pa2 << 16);
            fg = __uint_as_float(pa2 & 0xffff0000u);
            pl2 = bf2(S[2*kc+1][0] - f, S[2*kc+1][1] - fg);
            f = __uint_as_float(pa3 << 16);
            fg = __uint_as_float(pa3 & 0xffff0000u);
            pl3 = bf2(S[2*kc+1][2] - f, S[2*kc+1][3] - fg);

            #pragma unroll
            for (int j2 = 0; j2 < 4; ++j2) {
                uint32_t vh[4], vl[4];
                ldsm4t(vh[0], vh[1], vh[2], vh[3],
                       lda(sbase + bVh, kc * 16, j2 * 2, l));
                ldsm4t(vl[0], vl[1], vl[2], vl[3],
                       lda(sbase + bVl, kc * 16, j2 * 2, l));
                // B frag (dk j2*16+0..7): {r0, r1}; (+8..15): {r2, r3}
                mma16816(O[2*j2],   pa0, pa1, pa2, pa3, vh[0], vh[1]);
                mma16816(O[2*j2],   pa0, pa1, pa2, pa3, vl[0], vl[1]);
                mma16816(O[2*j2],   pl0, pl1, pl2, pl3, vh[0], vh[1]);
                mma16816(O[2*j2+1], pa0, pa1, pa2, pa3, vh[2], vh[3]);
                mma16816(O[2*j2+1], pa0, pa1, pa2, pa3, vl[2], vl[3]);
                mma16816(O[2*j2+1], pl0, pl1, pl2, pl3, vh[2], vh[3]);
            }
        }
        __syncthreads();   // before next iteration overwrites smem planes
    }

    // ---- epilogue: normalize and write
    float inv0 = 1.f / L0, inv1 = 1.f / L1;
    float* ob = g_att + qoff;
    #pragma unroll
    for (int j = 0; j < 8; ++j) {
        int col = j * 8 + kb;
        *(float2*)(ob + rr0 * DKH + col) = make_float2(O[j][0] * inv0, O[j][1] * inv0);
        *(float2*)(ob + rr1 * DKH + col) = make_float2(O[j][2] * inv1, O[j][3] * inv1);
    }
}

// ---------------------------------------------------------------------------
extern "C" void kernel_launch(void* const* d_in, const int* in_sizes, int n_in,
                              void* d_out, int out_size) {
    (void)in_sizes; (void)n_in; (void)out_size;
    const float* x   = (const float*)d_in[0];
    const float* Wq  = (const float*)d_in[1];
    const float* Wk  = (const float*)d_in[2];
    const float* Wv  = (const float*)d_in[3];
    const float* Wo  = (const float*)d_in[4];
    const int*   pos = (const int*)d_in[5];
    float* out = (float*)d_out;

    rope_table_kernel<<<(SEQ * 32 + 255) / 256, 256>>>(pos);

    dim3 ggrid(DIM / 128, MTOT / 128);   // (8, 64)
    gemm_wmma_kernel<0, 1><<<ggrid, 256>>>(x, Wq, nullptr);
    gemm_wmma_kernel<0, 2><<<ggrid, 256>>>(x, Wk, nullptr);
    gemm_wmma_kernel<0, 3><<<ggrid, 256>>>(x, Wv, nullptr);

    rope_split_kernel<<<(3 * NB * NH * SEQ * 32) / 256, 256>>>();

    attn_mma_kernel<<<dim3(SEQ / 64, NB * NH), 128>>>();

    gemm_wmma_kernel<1, 0><<<ggrid, 256>>>(nullptr, Wo, out);
}